// round 16
// baseline (speedup 1.0000x reference)
#include <cuda_runtime.h>
#include <math.h>

#define N_NODES 100000
#define N_EDGES 1600000
#define MAXN 0.996f          // (1 - 4e-3)/sqrt(1)
#define MINN 1e-15f

// ---------------- scratch (device globals: allocation-free) ----------------
__device__ __align__(256) float g_aggp[N_NODES * 64];
__device__ __align__(256) float g_aggn[N_NODES * 64];
__device__ float g_cntp[N_NODES];
__device__ float g_cntn[N_NODES];
__device__ float g_hb[2][64];
__device__ float g_hb2[2];
__device__ int   g_pe64;   // 1 if pos_edge_index is int64

typedef unsigned long long u64;

// ---------------- packed f32x2 helpers ----------------
__device__ __forceinline__ u64 splat(float s) {
    u64 r; asm("mov.b64 %0, {%1, %1};" : "=l"(r) : "f"(s)); return r;
}
__device__ __forceinline__ u64 ffma2(u64 a, u64 b, u64 c) {
    u64 d; asm("fma.rn.f32x2 %0, %1, %2, %3;" : "=l"(d) : "l"(a), "l"(b), "l"(c)); return d;
}
__device__ __forceinline__ void upk(u64 v, float& lo, float& hi) {
    asm("mov.b64 {%0, %1}, %2;" : "=f"(lo), "=f"(hi) : "l"(v));
}
__device__ __forceinline__ float wsum(float v) {
#pragma unroll
    for (int o = 16; o > 0; o >>= 1) v += __shfl_xor_sync(0xffffffffu, v, o);
    return v;
}

// scale s such that proj(mobius_matvec) = s * mx   (c = 1)
__device__ __forceinline__ float mm_scale(float in2, float mx2) {
    float xn  = fmaxf(sqrtf(in2), MINN);
    float mxt = sqrtf(mx2);
    float mxn = fmaxf(mxt, MINN);
    float art = atanhf(fminf(xn, 1.0f - 1e-7f));
    float t   = tanhf(mxn / xn * art);
    float s   = t / mxn;
    float rn  = fmaxf(t * (mxt / mxn), MINN);   // ||res|| for proj
    if (rn > MAXN) s *= MAXN / rn;
    return s;
}

// proj(mobius_add(s*mx, hb)) = fx*mx + fy*hb   (c = 1, analytic norms)
__device__ __forceinline__ void madd_coef(float s, float mx2, float dmh, float y2,
                                          float& fx, float& fy) {
    float xy  = s * dmh;
    float xx  = s * s * mx2;
    float a   = 1.0f + 2.0f * xy + y2;
    float b   = 1.0f - xx;
    float den = fmaxf(1.0f + 2.0f * xy + xx * y2, MINN);
    float on2 = fmaxf((a * a * xx + 2.0f * a * b * xy + b * b * y2) / (den * den), 0.0f);
    float on  = fmaxf(sqrtf(on2), MINN);
    float ps  = (on > MAXN) ? (MAXN / on) : 1.0f;
    fx = ps * a / den * s;
    fy = ps * b / den;
}

// ---------------- kernels ----------------
__global__ void zero_kernel() {
    int i = blockIdx.x * blockDim.x + threadIdx.x;
    float4 z = make_float4(0.f, 0.f, 0.f, 0.f);
    if (i < N_NODES * 16) {
        ((float4*)g_aggp)[i] = z;
        ((float4*)g_aggn)[i] = z;
    }
    if (i < N_NODES) { g_cntp[i] = 0.f; g_cntn[i] = 0.f; }
}

// hyp_bias = proj(expmap0(b)); also detect int64 pos edge index
__global__ void bias_kernel(const float* __restrict__ bp, const float* __restrict__ bn,
                            const int* __restrict__ pe) {
    int lane = threadIdx.x;
#pragma unroll
    for (int w = 0; w < 2; ++w) {
        const float* b = w ? bn : bp;
        float2 v = ((const float2*)b)[lane];
        float ss = wsum(v.x * v.x + v.y * v.y);
        float nt = sqrtf(ss);
        float nm = fmaxf(nt, MINN);
        float t  = tanhf(nm);
        float s  = t / nm;
        float un = fmaxf(t * (nt / nm), MINN);
        if (un > MAXN) s *= MAXN / un;
        g_hb[w][2 * lane]     = s * v.x;
        g_hb[w][2 * lane + 1] = s * v.y;
        if (lane == 0) g_hb2[w] = s * s * ss;
    }
    if (lane == 0) {
        // int64 detection: high words of first 16 int64 values are all 0
        int z = 0;
#pragma unroll
        for (int i = 0; i < 16; ++i) z |= pe[2 * i + 1];
        g_pe64 = (z == 0) ? 1 : 0;
    }
}

// 16 threads per edge; vector L2 reductions (no return)
__global__ void scatter_kernel(const float4* __restrict__ x4,
                               const int* __restrict__ pe,
                               const int* __restrict__ ne) {
    unsigned int tid = blockIdx.x * blockDim.x + threadIdx.x;
    int part = tid & 15;
    unsigned int e = tid >> 4;
    int src, dst;
    float* agg;
    float* cnt;
    if (e < (unsigned)N_EDGES) {                 // positive edges
        if (g_pe64) {
            src = (int)((const long long*)pe)[e];
            dst = (int)((const long long*)pe)[N_EDGES + e];
        } else {
            src = __ldg(pe + e);
            dst = __ldg(pe + N_EDGES + e);
        }
        agg = g_aggp; cnt = g_cntp;
    } else {                                     // negative edges (always int32)
        e -= N_EDGES;
        if (e >= (unsigned)N_EDGES) return;
        src = __ldg(ne + e);
        dst = __ldg(ne + N_EDGES + e);
        agg = g_aggn; cnt = g_cntn;
    }
    float4 v = __ldg(x4 + src * 16 + part);
    float* addr = agg + dst * 64 + part * 4;
    asm volatile("red.global.add.v4.f32 [%0], {%1, %2, %3, %4};"
                 :: "l"(addr), "f"(v.x), "f"(v.y), "f"(v.z), "f"(v.w) : "memory");
    if (part == 0) atomicAdd(cnt + dst, 1.0f);
}

#define WPB 8
#define NPI 4
#define NGROUPS ((N_NODES + NPI - 1) / NPI)
#define SMEM_BYTES (4 * 64 * 32 * 8 + WPB * NPI * 3 * 32 * 8)   // 64KB W + 24KB staging

__global__ void __launch_bounds__(256, 2) compute_kernel(
    const float* __restrict__ x,
    const float* __restrict__ W0, const float* __restrict__ W1,
    const float* __restrict__ W2, const float* __restrict__ W3,
    float* __restrict__ out)
{
    extern __shared__ u64 Wsm[];                 // [4][64][32] pairs {W[j][k], W[j+32][k]}
    float2* stage = (float2*)(Wsm + 4 * 64 * 32);
    int lane = threadIdx.x & 31;
    int warp = threadIdx.x >> 5;

    {   // stage W matrices, swizzled to conflict-free output-pair layout
        const float* Wm[4] = {W0, W1, W2, W3};
        float* Wf = (float*)Wsm;
        for (int idx = threadIdx.x; idx < 4 * 4096; idx += blockDim.x) {
            int m = idx >> 12, r = idx & 4095;
            int j = r >> 6, k = r & 63;
            Wf[m * 4096 + k * 64 + ((j & 31) << 1) + (j >> 5)] = Wm[m][r];
        }
    }
    __syncthreads();

    float hbp_l = g_hb[0][lane], hbp_h = g_hb[0][lane + 32];
    float hbn_l = g_hb[1][lane], hbn_h = g_hb[1][lane + 32];
    float hb2p = g_hb2[0], hb2n = g_hb2[1];

    const u64* Wl = Wsm + lane;
    float2* st = stage + warp * (NPI * 3 * 32);

    for (int g = blockIdx.x * WPB + warp; g < NGROUPS; g += gridDim.x * WPB) {
        int nb = g * NPI;
        float x2s[NPI], ap2s[NPI], an2s[NPI];
        __syncwarp();
#pragma unroll
        for (int i = 0; i < NPI; ++i) {
            int node = nb + i; if (node >= N_NODES) node = N_NODES - 1;
            float2 xv = ((const float2*)x)[node * 32 + lane];
            float ip = 1.0f / fmaxf(g_cntp[node], 1.0f);
            float2 av = ((const float2*)g_aggp)[node * 32 + lane];
            av.x *= ip; av.y *= ip;
            float im = 1.0f / fmaxf(g_cntn[node], 1.0f);
            float2 nv = ((const float2*)g_aggn)[node * 32 + lane];
            nv.x *= im; nv.y *= im;
            st[(i * 3 + 0) * 32 + lane] = xv;
            st[(i * 3 + 1) * 32 + lane] = av;
            st[(i * 3 + 2) * 32 + lane] = nv;
            x2s[i]  = wsum(xv.x * xv.x + xv.y * xv.y);
            ap2s[i] = wsum(av.x * av.x + av.y * av.y);
            an2s[i] = wsum(nv.x * nv.x + nv.y * nv.y);
        }
        __syncwarp();

        u64 a0[NPI], a1[NPI], a2[NPI], a3[NPI];
#pragma unroll
        for (int i = 0; i < NPI; ++i) { a0[i] = 0ull; a1[i] = 0ull; a2[i] = 0ull; a3[i] = 0ull; }

#pragma unroll 8
        for (int k2 = 0; k2 < 32; ++k2) {
            u64 w0  = Wl[0 * 2048 + k2 * 64];
            u64 w0b = Wl[0 * 2048 + k2 * 64 + 32];
            u64 w1  = Wl[1 * 2048 + k2 * 64];
            u64 w1b = Wl[1 * 2048 + k2 * 64 + 32];
            u64 w2  = Wl[2 * 2048 + k2 * 64];
            u64 w2b = Wl[2 * 2048 + k2 * 64 + 32];
            u64 w3  = Wl[3 * 2048 + k2 * 64];
            u64 w3b = Wl[3 * 2048 + k2 * 64 + 32];
#pragma unroll
            for (int i = 0; i < NPI; ++i) {
                float2 xv = st[(i * 3 + 0) * 32 + k2];
                float2 av = st[(i * 3 + 1) * 32 + k2];
                float2 nv = st[(i * 3 + 2) * 32 + k2];
                u64 sxl = splat(xv.x), sxh = splat(xv.y);
                u64 sal = splat(av.x), sah = splat(av.y);
                u64 snl = splat(nv.x), snh = splat(nv.y);
                a0[i] = ffma2(w0, sal, a0[i]); a0[i] = ffma2(w0b, sah, a0[i]);
                a1[i] = ffma2(w1, sxl, a1[i]); a1[i] = ffma2(w1b, sxh, a1[i]);
                a2[i] = ffma2(w2, snl, a2[i]); a2[i] = ffma2(w2b, snh, a2[i]);
                a3[i] = ffma2(w3, sxl, a3[i]); a3[i] = ffma2(w3b, sxh, a3[i]);
            }
        }

#pragma unroll
        for (int i = 0; i < NPI; ++i) {
            float pa_l, pa_h, px_l, px_h, na_l, na_h, nx_l, nx_h;
            upk(a0[i], pa_l, pa_h); upk(a1[i], px_l, px_h);
            upk(a2[i], na_l, na_h); upk(a3[i], nx_l, nx_h);
            float q_pa = wsum(pa_l * pa_l + pa_h * pa_h);
            float q_px = wsum(px_l * px_l + px_h * px_h);
            float q_na = wsum(na_l * na_l + na_h * na_h);
            float q_nx = wsum(nx_l * nx_l + nx_h * nx_h);
            float dpx  = wsum(px_l * hbp_l + px_h * hbp_h);
            float dnx  = wsum(nx_l * hbn_l + nx_h * hbn_h);
            float sPA = mm_scale(ap2s[i], q_pa);
            float sPX = mm_scale(x2s[i],  q_px);
            float sNA = mm_scale(an2s[i], q_na);
            float sNX = mm_scale(x2s[i],  q_nx);
            float fxp, fyp, fxn, fyn;
            madd_coef(sPX, q_px, dpx, hb2p, fxp, fyp);
            madd_coef(sNX, q_nx, dnx, hb2n, fxn, fyn);
            int node = nb + i;
            if (node < N_NODES) {
                float* o = out + (size_t)node * 128;
                o[lane]      = sPA * pa_l + fxp * px_l + fyp * hbp_l;
                o[lane + 32] = sPA * pa_h + fxp * px_h + fyp * hbp_h;
                o[lane + 64] = sNA * na_l + fxn * nx_l + fyn * hbn_l;
                o[lane + 96] = sNA * na_h + fxn * nx_h + fyn * hbn_h;
            }
        }
    }
}

extern "C" void kernel_launch(void* const* d_in, const int* in_sizes, int n_in,
                              void* d_out, int out_size) {
    const float* x    = (const float*)d_in[0];
    const float* Wp   = (const float*)d_in[1];
    const float* Wpcc = (const float*)d_in[2];
    const float* bp   = (const float*)d_in[3];
    const float* Wn   = (const float*)d_in[4];
    const float* Wncc = (const float*)d_in[5];
    const float* bn   = (const float*)d_in[6];
    const int*   pe   = (const int*)d_in[7];
    const int*   ne   = (const int*)d_in[8];
    float* out = (float*)d_out;

    cudaFuncSetAttribute(compute_kernel, cudaFuncAttributeMaxDynamicSharedMemorySize, SMEM_BYTES);

    zero_kernel<<<(N_NODES * 16 + 255) / 256, 256>>>();
    bias_kernel<<<1, 32>>>(bp, bn, pe);
    scatter_kernel<<<(2u * N_EDGES * 16u) / 256u, 256>>>((const float4*)x, pe, ne);
    compute_kernel<<<296, 256, SMEM_BYTES>>>(x, Wp, Wpcc, Wn, Wncc, out);
}

// round 17
// speedup vs baseline: 1.0858x; 1.0858x over previous
#include <cuda_runtime.h>
#include <math.h>

#define N_NODES 100000
#define N_EDGES 1600000
#define MAXN 0.996f          // (1 - 4e-3)/sqrt(1)
#define MINN 1e-15f

typedef unsigned long long u64;

// ---------------- scratch (device globals: allocation-free) ----------------
__device__ __align__(256) float g_aggp[N_NODES * 64];   // mean-aggregated pos
__device__ __align__(256) float g_aggn[N_NODES * 64];   // mean-aggregated neg
__device__ int g_degp[N_NODES];
__device__ int g_degn[N_NODES];
__device__ int g_rpp[N_NODES + 1];
__device__ int g_rpn[N_NODES + 1];
__device__ int g_curp[N_NODES];
__device__ int g_curn[N_NODES];
__device__ int g_srcp[N_EDGES];
__device__ int g_srcn[N_EDGES];
__device__ float g_hb[2][64];
__device__ float g_hb2[2];
__device__ int   g_pe64;   // 1 if pos_edge_index is int64

// ---------------- packed f32x2 helpers ----------------
__device__ __forceinline__ u64 ffma2(u64 a, u64 b, u64 c) {
    u64 d; asm("fma.rn.f32x2 %0, %1, %2, %3;" : "=l"(d) : "l"(a), "l"(b), "l"(c)); return d;
}
__device__ __forceinline__ float hadd(u64 v) {
    float lo, hi; asm("mov.b64 {%0, %1}, %2;" : "=f"(lo), "=f"(hi) : "l"(v));
    return lo + hi;
}
__device__ __forceinline__ float wsum(float v) {
#pragma unroll
    for (int o = 16; o > 0; o >>= 1) v += __shfl_xor_sync(0xffffffffu, v, o);
    return v;
}

// scale s such that proj(mobius_matvec) = s * mx   (c = 1)
__device__ __forceinline__ float mm_scale(float in2, float mx2) {
    float xn  = fmaxf(sqrtf(in2), MINN);
    float mxt = sqrtf(mx2);
    float mxn = fmaxf(mxt, MINN);
    float art = atanhf(fminf(xn, 1.0f - 1e-7f));
    float t   = tanhf(mxn / xn * art);
    float s   = t / mxn;
    float rn  = fmaxf(t * (mxt / mxn), MINN);   // ||res|| for proj
    if (rn > MAXN) s *= MAXN / rn;
    return s;
}

// proj(mobius_add(s*mx, hb)) = fx*mx + fy*hb   (c = 1, analytic norms)
__device__ __forceinline__ void madd_coef(float s, float mx2, float dmh, float y2,
                                          float& fx, float& fy) {
    float xy  = s * dmh;
    float xx  = s * s * mx2;
    float a   = 1.0f + 2.0f * xy + y2;
    float b   = 1.0f - xx;
    float den = fmaxf(1.0f + 2.0f * xy + xx * y2, MINN);
    float on2 = fmaxf((a * a * xx + 2.0f * a * b * xy + b * b * y2) / (den * den), 0.0f);
    float on  = fmaxf(sqrtf(on2), MINN);
    float ps  = (on > MAXN) ? (MAXN / on) : 1.0f;
    fx = ps * a / den * s;
    fy = ps * b / den;
}

// ---------------- small kernels ----------------
__global__ void zero_deg_kernel() {
    int i = blockIdx.x * blockDim.x + threadIdx.x;
    if (i < N_NODES) { g_degp[i] = 0; g_degn[i] = 0; }
}

// hyp_bias = proj(expmap0(b)); also detect int64 pos edge index
__global__ void bias_kernel(const float* __restrict__ bp, const float* __restrict__ bn,
                            const int* __restrict__ pe) {
    int lane = threadIdx.x;
#pragma unroll
    for (int w = 0; w < 2; ++w) {
        const float* b = w ? bn : bp;
        float2 v = ((const float2*)b)[lane];
        float ss = wsum(v.x * v.x + v.y * v.y);
        float nt = sqrtf(ss);
        float nm = fmaxf(nt, MINN);
        float t  = tanhf(nm);
        float s  = t / nm;
        float un = fmaxf(t * (nt / nm), MINN);
        if (un > MAXN) s *= MAXN / un;
        g_hb[w][2 * lane]     = s * v.x;
        g_hb[w][2 * lane + 1] = s * v.y;
        if (lane == 0) g_hb2[w] = s * s * ss;
    }
    if (lane == 0) {
        int z = 0;
#pragma unroll
        for (int i = 0; i < 16; ++i) z |= pe[2 * i + 1];
        g_pe64 = (z == 0) ? 1 : 0;
    }
}

__global__ void hist_kernel(const int* __restrict__ pe, const int* __restrict__ ne) {
    unsigned t = blockIdx.x * blockDim.x + threadIdx.x;
    if (t < (unsigned)N_EDGES) {
        int dst = g_pe64 ? (int)((const long long*)pe)[N_EDGES + t]
                         : __ldg(pe + N_EDGES + t);
        atomicAdd(&g_degp[dst], 1);
    } else {
        t -= N_EDGES;
        if (t >= (unsigned)N_EDGES) return;
        int dst = __ldg(ne + N_EDGES + t);
        atomicAdd(&g_degn[dst], 1);
    }
}

// exclusive scan of deg -> rowptr (+ total at [N]); cursor = rowptr
__global__ void scan_kernel() {
    int a = blockIdx.x;
    const int* deg = a ? g_degn : g_degp;
    int* rp  = a ? g_rpn : g_rpp;
    int* cur = a ? g_curn : g_curp;
    __shared__ int wsums[32];
    int tid = threadIdx.x, lane = tid & 31, w = tid >> 5;
    int carry = 0;
    for (int base = 0; base < N_NODES; base += 4096) {
        int i0 = base + tid * 4;
        int v0 = (i0 + 0 < N_NODES) ? deg[i0 + 0] : 0;
        int v1 = (i0 + 1 < N_NODES) ? deg[i0 + 1] : 0;
        int v2 = (i0 + 2 < N_NODES) ? deg[i0 + 2] : 0;
        int v3 = (i0 + 3 < N_NODES) ? deg[i0 + 3] : 0;
        int s = v0 + v1 + v2 + v3;
        int sc = s;
#pragma unroll
        for (int o = 1; o < 32; o <<= 1) {
            int t = __shfl_up_sync(0xffffffffu, sc, o);
            if (lane >= o) sc += t;
        }
        if (lane == 31) wsums[w] = sc;
        __syncthreads();
        if (w == 0) {
            int t = wsums[lane];
#pragma unroll
            for (int o = 1; o < 32; o <<= 1) {
                int u = __shfl_up_sync(0xffffffffu, t, o);
                if (lane >= o) t += u;
            }
            wsums[lane] = t;
        }
        __syncthreads();
        int run = carry + sc - s + (w ? wsums[w - 1] : 0);
        if (i0 + 0 < N_NODES) { rp[i0 + 0] = run; cur[i0 + 0] = run; run += v0; }
        if (i0 + 1 < N_NODES) { rp[i0 + 1] = run; cur[i0 + 1] = run; run += v1; }
        if (i0 + 2 < N_NODES) { rp[i0 + 2] = run; cur[i0 + 2] = run; run += v2; }
        if (i0 + 3 < N_NODES) { rp[i0 + 3] = run; cur[i0 + 3] = run; run += v3; }
        carry += wsums[31];
        __syncthreads();
    }
    if (tid == 0) rp[N_NODES] = carry;
}

__global__ void fill_kernel(const int* __restrict__ pe, const int* __restrict__ ne) {
    unsigned t = blockIdx.x * blockDim.x + threadIdx.x;
    if (t < (unsigned)N_EDGES) {
        int src, dst;
        if (g_pe64) {
            src = (int)((const long long*)pe)[t];
            dst = (int)((const long long*)pe)[N_EDGES + t];
        } else {
            src = __ldg(pe + t);
            dst = __ldg(pe + N_EDGES + t);
        }
        int slot = atomicAdd(&g_curp[dst], 1);
        g_srcp[slot] = src;
    } else {
        t -= N_EDGES;
        if (t >= (unsigned)N_EDGES) return;
        int src = __ldg(ne + t);
        int dst = __ldg(ne + N_EDGES + t);
        int slot = atomicAdd(&g_curn[dst], 1);
        g_srcn[slot] = src;
    }
}

// warp per (node,set): gather-sum in-edge src rows, write mean
__global__ void agg_kernel(const float2* __restrict__ xs) {
    int gw = (blockIdx.x * blockDim.x + threadIdx.x) >> 5;
    int lane = threadIdx.x & 31;
    int set = gw & 1;
    int node = gw >> 1;
    if (node >= N_NODES) return;
    const int* rp = set ? g_rpn : g_rpp;
    const int* sl = set ? g_srcn : g_srcp;
    float2* agg = set ? (float2*)g_aggn : (float2*)g_aggp;
    int beg = rp[node], end = rp[node + 1];
    float accx = 0.f, accy = 0.f;
    for (int b = beg; b < end; b += 32) {
        int cnt = min(32, end - b);
        int idx = (lane < cnt) ? __ldg(sl + b + lane) : 0;
        int e = 0;
        for (; e + 4 <= cnt; e += 4) {
            int s0 = __shfl_sync(0xffffffffu, idx, e);
            int s1 = __shfl_sync(0xffffffffu, idx, e + 1);
            int s2 = __shfl_sync(0xffffffffu, idx, e + 2);
            int s3 = __shfl_sync(0xffffffffu, idx, e + 3);
            float2 a = __ldg(xs + s0 * 32 + lane);
            float2 bb = __ldg(xs + s1 * 32 + lane);
            float2 c = __ldg(xs + s2 * 32 + lane);
            float2 d = __ldg(xs + s3 * 32 + lane);
            accx += (a.x + bb.x) + (c.x + d.x);
            accy += (a.y + bb.y) + (c.y + d.y);
        }
        for (; e < cnt; ++e) {
            int s = __shfl_sync(0xffffffffu, idx, e);
            float2 a = __ldg(xs + s * 32 + lane);
            accx += a.x; accy += a.y;
        }
    }
    float inv = (end > beg) ? 1.0f / (float)(end - beg) : 0.0f;
    float2 o; o.x = accx * inv; o.y = accy * inv;
    agg[node * 32 + lane] = o;
}

// ---------------- compute (k-packed FFMA2) ----------------
#define WPB 8
#define NPI 4
#define NGROUPS ((N_NODES + NPI - 1) / NPI)
#define SMEM_W (4 * 32 * 64 * 8)                 // 64KB: [m][k2][j] u64 pairs over k
#define SMEM_STAGE (WPB * NPI * 3 * 32 * 8)      // 24KB: float2 pairs over k
#define SMEM_BYTES (SMEM_W + SMEM_STAGE)

__global__ void __launch_bounds__(256, 2) compute_kernel(
    const float* __restrict__ x,
    const float* __restrict__ W0, const float* __restrict__ W1,
    const float* __restrict__ W2, const float* __restrict__ W3,
    float* __restrict__ out)
{
    extern __shared__ u64 Wsm[];                 // [4][32][64] u64
    u64* stageu = Wsm + 4 * 32 * 64;             // [warp][NPI][3][32] u64 (float2)
    int lane = threadIdx.x & 31;
    int warp = threadIdx.x >> 5;

    {   // Wf[((m*32 + k/2)*64 + j)*2 + (k&1)] = W[m][j][k]
        const float* Wm[4] = {W0, W1, W2, W3};
        float* Wf = (float*)Wsm;
        for (int idx = threadIdx.x; idx < 4 * 4096; idx += blockDim.x) {
            int m = idx >> 12, r = idx & 4095;
            int j = r >> 6, k = r & 63;
            Wf[((m * 32 + (k >> 1)) * 64 + j) * 2 + (k & 1)] = Wm[m][r];
        }
    }
    __syncthreads();

    float hbp_l = g_hb[0][lane], hbp_h = g_hb[0][lane + 32];
    float hbn_l = g_hb[1][lane], hbn_h = g_hb[1][lane + 32];
    float hb2p = g_hb2[0], hb2n = g_hb2[1];

    const u64* WL = Wsm + lane;                  // + m*2048 + k2*64 (+32 for j+32)
    u64* st = stageu + warp * (NPI * 3 * 32);

    for (int g = blockIdx.x * WPB + warp; g < NGROUPS; g += gridDim.x * WPB) {
        int nb = g * NPI;
        float x2s[NPI], ap2s[NPI], an2s[NPI];
        __syncwarp();
#pragma unroll
        for (int i = 0; i < NPI; ++i) {
            int node = nb + i; if (node >= N_NODES) node = N_NODES - 1;
            float2 xv = __ldg((const float2*)x + node * 32 + lane);
            float2 av = __ldg((const float2*)g_aggp + node * 32 + lane);
            float2 nv = __ldg((const float2*)g_aggn + node * 32 + lane);
            ((float2*)st)[(i * 3 + 0) * 32 + lane] = xv;
            ((float2*)st)[(i * 3 + 1) * 32 + lane] = av;
            ((float2*)st)[(i * 3 + 2) * 32 + lane] = nv;
            x2s[i]  = wsum(xv.x * xv.x + xv.y * xv.y);
            ap2s[i] = wsum(av.x * av.x + av.y * av.y);
            an2s[i] = wsum(nv.x * nv.x + nv.y * nv.y);
        }
        __syncwarp();

        u64 A[NPI][8];
#pragma unroll
        for (int i = 0; i < NPI; ++i)
#pragma unroll
            for (int m = 0; m < 8; ++m) A[i][m] = 0ull;

#pragma unroll 4
        for (int k2 = 0; k2 < 32; ++k2) {
            u64 w0a = WL[0 * 2048 + k2 * 64];
            u64 w0b = WL[0 * 2048 + k2 * 64 + 32];
            u64 w1a = WL[1 * 2048 + k2 * 64];
            u64 w1b = WL[1 * 2048 + k2 * 64 + 32];
            u64 w2a = WL[2 * 2048 + k2 * 64];
            u64 w2b = WL[2 * 2048 + k2 * 64 + 32];
            u64 w3a = WL[3 * 2048 + k2 * 64];
            u64 w3b = WL[3 * 2048 + k2 * 64 + 32];
#pragma unroll
            for (int i = 0; i < NPI; ++i) {
                u64 xv = st[(i * 3 + 0) * 32 + k2];
                u64 av = st[(i * 3 + 1) * 32 + k2];
                u64 nv = st[(i * 3 + 2) * 32 + k2];
                A[i][0] = ffma2(w0a, av, A[i][0]);
                A[i][1] = ffma2(w0b, av, A[i][1]);
                A[i][2] = ffma2(w1a, xv, A[i][2]);
                A[i][3] = ffma2(w1b, xv, A[i][3]);
                A[i][4] = ffma2(w2a, nv, A[i][4]);
                A[i][5] = ffma2(w2b, nv, A[i][5]);
                A[i][6] = ffma2(w3a, xv, A[i][6]);
                A[i][7] = ffma2(w3b, xv, A[i][7]);
            }
        }

#pragma unroll
        for (int i = 0; i < NPI; ++i) {
            float pa_l = hadd(A[i][0]), pa_h = hadd(A[i][1]);
            float px_l = hadd(A[i][2]), px_h = hadd(A[i][3]);
            float na_l = hadd(A[i][4]), na_h = hadd(A[i][5]);
            float nx_l = hadd(A[i][6]), nx_h = hadd(A[i][7]);
            float q_pa = wsum(pa_l * pa_l + pa_h * pa_h);
            float q_px = wsum(px_l * px_l + px_h * px_h);
            float q_na = wsum(na_l * na_l + na_h * na_h);
            float q_nx = wsum(nx_l * nx_l + nx_h * nx_h);
            float dpx  = wsum(px_l * hbp_l + px_h * hbp_h);
            float dnx  = wsum(nx_l * hbn_l + nx_h * hbn_h);
            float sPA = mm_scale(ap2s[i], q_pa);
            float sPX = mm_scale(x2s[i],  q_px);
            float sNA = mm_scale(an2s[i], q_na);
            float sNX = mm_scale(x2s[i],  q_nx);
            float fxp, fyp, fxn, fyn;
            madd_coef(sPX, q_px, dpx, hb2p, fxp, fyp);
            madd_coef(sNX, q_nx, dnx, hb2n, fxn, fyn);
            int node = nb + i;
            if (node < N_NODES) {
                float* o = out + (size_t)node * 128;
                o[lane]      = sPA * pa_l + fxp * px_l + fyp * hbp_l;
                o[lane + 32] = sPA * pa_h + fxp * px_h + fyp * hbp_h;
                o[lane + 64] = sNA * na_l + fxn * nx_l + fyn * hbn_l;
                o[lane + 96] = sNA * na_h + fxn * nx_h + fyn * hbn_h;
            }
        }
    }
}

extern "C" void kernel_launch(void* const* d_in, const int* in_sizes, int n_in,
                              void* d_out, int out_size) {
    const float* x    = (const float*)d_in[0];
    const float* Wp   = (const float*)d_in[1];
    const float* Wpcc = (const float*)d_in[2];
    const float* bp   = (const float*)d_in[3];
    const float* Wn   = (const float*)d_in[4];
    const float* Wncc = (const float*)d_in[5];
    const float* bn   = (const float*)d_in[6];
    const int*   pe   = (const int*)d_in[7];
    const int*   ne   = (const int*)d_in[8];
    float* out = (float*)d_out;

    cudaFuncSetAttribute(compute_kernel, cudaFuncAttributeMaxDynamicSharedMemorySize, SMEM_BYTES);

    bias_kernel<<<1, 32>>>(bp, bn, pe);                 // sets g_pe64 + hyp bias
    zero_deg_kernel<<<(N_NODES + 255) / 256, 256>>>();
    hist_kernel<<<(2 * N_EDGES) / 256, 256>>>(pe, ne);
    scan_kernel<<<2, 1024>>>();
    fill_kernel<<<(2 * N_EDGES) / 256, 256>>>(pe, ne);
    agg_kernel<<<(2 * N_NODES) / 8, 256>>>((const float2*)x);
    compute_kernel<<<296, 256, SMEM_BYTES>>>(x, Wp, Wpcc, Wn, Wncc, out);
}